// round 12
// baseline (speedup 1.0000x reference)
#include <cuda_runtime.h>
#include <cuda_bf16.h>
#include <cuda_fp16.h>
#include <stdint.h>

// ---------------------------------------------------------------------------
// GCN 2-layer:  out = Anorm @ relu(Anorm @ (x@W1) + b1) @ W2 + b2
// Layer 2 via linearity: (Anorm @ h1relu) @ W2 + b2.
// R11: plain fp16 tensor-core GEMMs (A and B both single fp16, fp32 accum).
// Error budget: ~2.8e-4 RMS per GEMM input rounding, quadrature total ~4.6e-4
// vs 1e-3 gate. Tensor work halved vs R10's 2-chain split.
// (tcgen05 unavailable: harness compiles compute_103 PTX which rejects it.)
// ---------------------------------------------------------------------------

#define N_NODES 50000
#define M_PAD   50048
#define MAX_E   1600000
#define MAX_CSR (MAX_E + N_NODES)
#define F_HID   400
#define K1      512
#define N1P     512
#define K2P     416
#define N2P     896
#define SPLIT_R 25088          // agg2/GEMM2 chunk boundary (196 * 128)

// GEMM tiling
#define BM 128
#define BN 128
#define BK 32
#define AP 40                  // smem A row pitch (halves): 80B, conflict-free ldmatrix
#define BP 136                 // smem B row pitch (halves): 272B, conflict-free ldmatrix
#define GEMM_SMEM ((2*BM*AP + 2*BK*BP) * 2)   // 37888 bytes

// ------------------------------- scratch -----------------------------------
__device__ __half g_h1h[(size_t)N_NODES * F_HID];    // x@W1 (fp16)
__device__ __half g_agg1h[(size_t)N_NODES * F_HID];  // relu(agg(h1)+b1) (fp16)
__device__ __half g_xh[(size_t)M_PAD * K1];          // x (fp16)
__device__ __half g_a2h[(size_t)M_PAD * K2P];        // agg2 (fp16); pad cols stay 0
__device__ __half g_w1h[K1 * N1P];                   // W1 fp16
__device__ __half g_w2h[K2P * N2P];                  // W2 fp16
__device__ float g_dinv[N_NODES];
__device__ int   g_deg[N_NODES];
__device__ int   g_fill[N_NODES];
__device__ int   g_rowptr[N_NODES + 1];
__device__ int   g_csr[MAX_CSR];
__device__ int   g_bsums[512];
__device__ int   g_is64;

// ---------------------------------------------------------------------------
// edge dtype detection (int32 vs int64 delivery)
// ---------------------------------------------------------------------------
__global__ void k_detect(const void* __restrict__ ei) {
    if (threadIdx.x == 0 && blockIdx.x == 0) {
        const long long* p = (const long long*)ei;
        int ok64 = 1;
#pragma unroll
        for (int i = 0; i < 16; i++) {
            long long v = p[i];
            if (v < 0 || v >= N_NODES) ok64 = 0;
        }
        g_is64 = ok64;
    }
}

__device__ __forceinline__ int edge_at(const void* ei, size_t idx) {
    if (g_is64) return (int)((const long long*)ei)[idx];
    return ((const int*)ei)[idx];
}

// ---------------------------------------------------------------------------
// degree / dinv
// ---------------------------------------------------------------------------
__global__ void k_init(int n) {
    int i = blockIdx.x * blockDim.x + threadIdx.x;
    if (i < n) { g_deg[i] = 1; g_fill[i] = 0; }
}

__global__ void k_count_deg(const void* __restrict__ ei, int E) {
    int i = blockIdx.x * blockDim.x + threadIdx.x;
    if (i < E) {
        int d = edge_at(ei, (size_t)E + i);
        if ((unsigned)d < (unsigned)N_NODES) atomicAdd(&g_deg[d], 1);
    }
}

__global__ void k_dinv(int n) {
    int i = blockIdx.x * blockDim.x + threadIdx.x;
    if (i < n) g_dinv[i] = rsqrtf((float)g_deg[i]);
}

// ---------------------------------------------------------------------------
// exclusive scan of g_deg -> g_rowptr
// ---------------------------------------------------------------------------
__device__ __forceinline__ int warp_incl_scan(int v) {
#pragma unroll
    for (int o = 1; o < 32; o <<= 1) {
        int t = __shfl_up_sync(0xffffffffu, v, o);
        if ((threadIdx.x & 31) >= o) v += t;
    }
    return v;
}

__global__ void k_scan_blocks(const int* __restrict__ in, int* __restrict__ out,
                              int* __restrict__ bsums, int n) {
    __shared__ int wsum[8];
    int i = blockIdx.x * 256 + threadIdx.x;
    int v = (i < n) ? in[i] : 0;
    int inc = warp_incl_scan(v);
    int lane = threadIdx.x & 31, w = threadIdx.x >> 5;
    if (lane == 31) wsum[w] = inc;
    __syncthreads();
    if (w == 0) {
        int s = (lane < 8) ? wsum[lane] : 0;
        s = warp_incl_scan(s);
        if (lane < 8) wsum[lane] = s;
    }
    __syncthreads();
    int off = (w > 0) ? wsum[w - 1] : 0;
    if (i < n) out[i] = off + inc - v;
    if (threadIdx.x == 255) bsums[blockIdx.x] = off + inc;
}

__global__ void k_scan_sums(int* __restrict__ bsums, int nb, int* __restrict__ total_out) {
    __shared__ int wsum[8];
    int v = (threadIdx.x < nb) ? bsums[threadIdx.x] : 0;
    int inc = warp_incl_scan(v);
    int lane = threadIdx.x & 31, w = threadIdx.x >> 5;
    if (lane == 31) wsum[w] = inc;
    __syncthreads();
    if (w == 0) {
        int s = (lane < 8) ? wsum[lane] : 0;
        s = warp_incl_scan(s);
        if (lane < 8) wsum[lane] = s;
    }
    __syncthreads();
    int off = (w > 0) ? wsum[w - 1] : 0;
    if (threadIdx.x < nb) bsums[threadIdx.x] = off + inc - v;
    if (threadIdx.x == 255) *total_out = off + inc;
}

__global__ void k_scan_add(int* __restrict__ out, const int* __restrict__ bsums, int n) {
    int i = blockIdx.x * 256 + threadIdx.x;
    if (i < n) out[i] += bsums[blockIdx.x];
}

// ---------------------------------------------------------------------------
// CSR fill
// ---------------------------------------------------------------------------
__global__ void k_fill_csr(const void* __restrict__ ei, int E, int n) {
    int i = blockIdx.x * blockDim.x + threadIdx.x;
    int total = E + n;
    if (i >= total) return;
    int s, d;
    if (i < E) {
        s = edge_at(ei, i);
        d = edge_at(ei, (size_t)E + i);
        if ((unsigned)s >= (unsigned)n || (unsigned)d >= (unsigned)n) return;
    } else {
        s = d = i - E;
    }
    int pos = atomicAdd(&g_fill[d], 1);
    g_csr[g_rowptr[d] + pos] = s;
}

// ---------------------------------------------------------------------------
// fp16 conversions
// ---------------------------------------------------------------------------
__global__ void k_conv_x(const float* __restrict__ x, int total) {
    int i = blockIdx.x * blockDim.x + threadIdx.x;
    if (i < total) g_xh[i] = __float2half(x[i]);
}

__global__ void k_conv_w1(const float* __restrict__ W1) {
    int i = blockIdx.x * blockDim.x + threadIdx.x;
    if (i < K1 * N1P) {
        int k = i / N1P, n = i % N1P;
        float v = (n < F_HID) ? W1[k * F_HID + n] : 0.f;
        g_w1h[i] = __float2half(v);
    }
}

__global__ void k_conv_w2(const float* __restrict__ W2, int N2real) {
    int i = blockIdx.x * blockDim.x + threadIdx.x;
    if (i < K2P * N2P) {
        int k = i / N2P, n = i % N2P;
        float v = (k < F_HID && n < N2real) ? W2[k * N2real + n] : 0.f;
        g_w2h[i] = __float2half(v);
    }
}

// ---------------------------------------------------------------------------
// plain fp16 tensor-core GEMM:  C = A * B (+bias), fp32 accumulate
// ---------------------------------------------------------------------------
__device__ __forceinline__ void cp16(void* dst, const void* src) {
    unsigned d = (unsigned)__cvta_generic_to_shared(dst);
    asm volatile("cp.async.cg.shared.global [%0], [%1], 16;\n" :: "r"(d), "l"(src));
}

__device__ __forceinline__ void ldmA(uint32_t* a, const __half* p) {
    unsigned addr = (unsigned)__cvta_generic_to_shared(p);
    asm volatile("ldmatrix.sync.aligned.m8n8.x4.shared.b16 {%0,%1,%2,%3}, [%4];"
                 : "=r"(a[0]), "=r"(a[1]), "=r"(a[2]), "=r"(a[3]) : "r"(addr));
}

__device__ __forceinline__ void ldmB(uint32_t* b, const __half* p) {
    unsigned addr = (unsigned)__cvta_generic_to_shared(p);
    asm volatile("ldmatrix.sync.aligned.m8n8.x2.trans.shared.b16 {%0,%1}, [%2];"
                 : "=r"(b[0]), "=r"(b[1]) : "r"(addr));
}

__device__ __forceinline__ void mma_fp16(float* c, const uint32_t* a, const uint32_t* b) {
    asm volatile("mma.sync.aligned.m16n8k16.row.col.f32.f16.f16.f32 "
                 "{%0,%1,%2,%3}, {%4,%5,%6,%7}, {%8,%9}, {%0,%1,%2,%3};"
                 : "+f"(c[0]), "+f"(c[1]), "+f"(c[2]), "+f"(c[3])
                 : "r"(a[0]), "r"(a[1]), "r"(a[2]), "r"(a[3]), "r"(b[0]), "r"(b[1]));
}

template <bool BIAS, bool HOUT>
__global__ __launch_bounds__(256, 1) void k_mma_gemm(
    const __half* __restrict__ A, const __half* __restrict__ B,
    const float* __restrict__ bias, float* __restrict__ C, __half* __restrict__ Ch,
    int M, int Nreal, int Nphys, int K) {
    extern __shared__ __half smem[];
    __half* sA = smem;                       // 2 stages * BM*AP
    __half* sB = sA + 2 * BM * AP;           // 2 stages * BK*BP

    int tid = threadIdx.x;
    int lane = tid & 31, wid = tid >> 5;
    int wm = (wid >> 2) * 64;
    int wn = (wid & 3) * 32;
    int bm = blockIdx.y * BM, bn = blockIdx.x * BN;

    float acc[4][4][4];
#pragma unroll
    for (int i = 0; i < 4; i++)
#pragma unroll
        for (int j = 0; j < 4; j++)
#pragma unroll
            for (int k = 0; k < 4; k++) acc[i][j][k] = 0.f;

    const int nk = K / BK;

    auto load_stage = [&](int st, int kt) {
        __half* sa = sA + st * BM * AP;
        __half* sb = sB + st * BK * BP;
#pragma unroll
        for (int i = 0; i < 2; i++) {
            int q = tid + i * 256;           // 512 chunks: 128 rows x 4x16B
            int r = q >> 2, c = q & 3;
            size_t goff = (size_t)(bm + r) * K + kt * BK + c * 8;
            cp16(sa + r * AP + c * 8, A + goff);
        }
#pragma unroll
        for (int i = 0; i < 2; i++) {
            int q = tid + i * 256;           // 512 chunks: 32 rows x 16x16B
            int r = q >> 4, c = q & 15;
            size_t goff = (size_t)(kt * BK + r) * Nphys + bn + c * 8;
            cp16(sb + r * BP + c * 8, B + goff);
        }
        asm volatile("cp.async.commit_group;\n");
    };

    load_stage(0, 0);

    for (int kt = 0; kt < nk; kt++) {
        if (kt + 1 < nk) {
            load_stage((kt + 1) & 1, kt + 1);
            asm volatile("cp.async.wait_group 1;\n");
        } else {
            asm volatile("cp.async.wait_group 0;\n");
        }
        __syncthreads();

        int st = kt & 1;
        const __half* sa = sA + st * BM * AP;
        const __half* sb = sB + st * BK * BP;

#pragma unroll
        for (int ks = 0; ks < 2; ks++) {
            uint32_t Af[4][4], Bf[4][2];
            int arow = (lane & 15), ahalf = (lane >> 4);
#pragma unroll
            for (int mt = 0; mt < 4; mt++) {
                const __half* pa =
                    sa + (size_t)(wm + mt * 16 + arow) * AP + ks * 16 + ahalf * 8;
                ldmA(Af[mt], pa);
            }
#pragma unroll
            for (int nt = 0; nt < 4; nt++) {
                const __half* pb =
                    sb + (size_t)(ks * 16 + (lane & 15)) * BP + wn + nt * 8;
                ldmB(Bf[nt], pb);
            }
#pragma unroll
            for (int mt = 0; mt < 4; mt++)
#pragma unroll
                for (int nt = 0; nt < 4; nt++)
                    mma_fp16(acc[mt][nt], Af[mt], Bf[nt]);
        }
        __syncthreads();
    }

#pragma unroll
    for (int mt = 0; mt < 4; mt++) {
#pragma unroll
        for (int nt = 0; nt < 4; nt++) {
#pragma unroll
            for (int i = 0; i < 4; i++) {
                int row = bm + wm + mt * 16 + (lane >> 2) + (i >> 1) * 8;
                int col = bn + wn + nt * 8 + (lane & 3) * 2 + (i & 1);
                if (row < M && col < Nreal) {
                    float v = acc[mt][nt][i];
                    if (BIAS) v += bias[col];
                    if (HOUT) Ch[(size_t)row * Nreal + col] = __float2half(v);
                    else      C[(size_t)row * Nreal + col] = v;
                }
            }
        }
    }
}

// ---------------------------------------------------------------------------
// CSR aggregation over F=400 fp16 features, one block (128 thr) per node.
// 100 lanes x uint2 (4 halves, LDG.64) per edge; fp32 accumulation.
// OS = output row stride (F_HID for agg1, K2P for agg2).
// ---------------------------------------------------------------------------
template <bool RELU>
__global__ __launch_bounds__(128) void k_aggregate(
    const __half* __restrict__ H, const float* __restrict__ bias,
    __half* __restrict__ outH, int OS, int node0) {
    __shared__ int   s_idx[128];
    __shared__ float s_w[128];

    int node = blockIdx.x + node0;
    int tid = threadIdx.x;
    int start = g_rowptr[node], end = g_rowptr[node + 1];
    float dd = g_dinv[node];

    float4 acc = make_float4(0.f, 0.f, 0.f, 0.f);
    const bool active = tid < (F_HID / 4);   // 100 uint2 lanes

    for (int base = start; base < end; base += 128) {
        int cnt = min(128, end - base);
        if (tid < cnt) {
            int s = g_csr[base + tid];
            s_idx[tid] = s;
            s_w[tid] = g_dinv[s] * dd;
        }
        __syncthreads();
        if (active) {
            int j = 0;
            for (; j + 4 <= cnt; j += 4) {
                uint2 u0 = ((const uint2*)(H + (size_t)s_idx[j + 0] * F_HID))[tid];
                uint2 u1 = ((const uint2*)(H + (size_t)s_idx[j + 1] * F_HID))[tid];
                uint2 u2 = ((const uint2*)(H + (size_t)s_idx[j + 2] * F_HID))[tid];
                uint2 u3 = ((const uint2*)(H + (size_t)s_idx[j + 3] * F_HID))[tid];
                float w0 = s_w[j + 0], w1 = s_w[j + 1];
                float w2 = s_w[j + 2], w3 = s_w[j + 3];
                float2 a0 = __half22float2(*(__half2*)&u0.x);
                float2 b0 = __half22float2(*(__half2*)&u0.y);
                float2 a1 = __half22float2(*(__half2*)&u1.x);
                float2 b1 = __half22float2(*(__half2*)&u1.y);
                float2 a2 = __half22float2(*(__half2*)&u2.x);
                float2 b2 = __half22float2(*(__half2*)&u2.y);
                float2 a3 = __half22float2(*(__half2*)&u3.x);
                float2 b3 = __half22float2(*(__half2*)&u3.y);
                acc.x += a0.x * w0; acc.y += a0.y * w0;
                acc.z += b0.x * w0; acc.w += b0.y * w0;
                acc.x += a1.x * w1; acc.y += a1.y * w1;
                acc.z += b1.x * w1; acc.w += b1.y * w1;
                acc.x += a2.x * w2; acc.y += a2.y * w2;
                acc.z += b2.x * w2; acc.w += b2.y * w2;
                acc.x += a3.x * w3; acc.y += a3.y * w3;
                acc.z += b3.x * w3; acc.w += b3.y * w3;
            }
            for (; j < cnt; j++) {
                uint2 u0 = ((const uint2*)(H + (size_t)s_idx[j] * F_HID))[tid];
                float w0 = s_w[j];
                float2 a0 = __half22float2(*(__half2*)&u0.x);
                float2 b0 = __half22float2(*(__half2*)&u0.y);
                acc.x += a0.x * w0; acc.y += a0.y * w0;
                acc.z += b0.x * w0; acc.w += b0.y * w0;
            }
        }
        __syncthreads();
    }

    if (active) {
        if (bias) {
            float4 b = ((const float4*)bias)[tid];
            acc.x += b.x; acc.y += b.y; acc.z += b.z; acc.w += b.w;
        }
        if (RELU) {
            acc.x = fmaxf(acc.x, 0.f); acc.y = fmaxf(acc.y, 0.f);
            acc.z = fmaxf(acc.z, 0.f); acc.w = fmaxf(acc.w, 0.f);
        }
        __half2 h01 = __floats2half2_rn(acc.x, acc.y);
        __half2 h23 = __floats2half2_rn(acc.z, acc.w);
        uint2 u;
        u.x = *(uint32_t*)&h01; u.y = *(uint32_t*)&h23;
        *(uint2*)(outH + (size_t)node * OS + tid * 4) = u;
    }
}

// ---------------------------------------------------------------------------
// launch
// ---------------------------------------------------------------------------
extern "C" void kernel_launch(void* const* d_in, const int* in_sizes, int n_in,
                              void* d_out, int out_size) {
    const float* x  = (const float*)d_in[0];
    const void*  ei = d_in[1];
    const float* W1 = (const float*)d_in[2];
    const float* b1 = (const float*)d_in[3];
    const float* W2 = (const float*)d_in[4];
    const float* b2 = (const float*)d_in[5];
    float* out = (float*)d_out;

    const int N = N_NODES;
    const int E = in_sizes[1] / 2;
    const int H2 = in_sizes[5];                       // 800

    __half *h1h, *agg1h, *xh, *a2h, *w1h, *w2h;
    int *deg, *rowptr, *bsums;
    cudaGetSymbolAddress((void**)&h1h, g_h1h);
    cudaGetSymbolAddress((void**)&agg1h, g_agg1h);
    cudaGetSymbolAddress((void**)&xh, g_xh);
    cudaGetSymbolAddress((void**)&a2h, g_a2h);
    cudaGetSymbolAddress((void**)&w1h, g_w1h);
    cudaGetSymbolAddress((void**)&w2h, g_w2h);
    cudaGetSymbolAddress((void**)&deg, g_deg);
    cudaGetSymbolAddress((void**)&rowptr, g_rowptr);
    cudaGetSymbolAddress((void**)&bsums, g_bsums);

    static int inited = 0;
    static cudaStream_t s2;
    static cudaEvent_t evRoot, evCsr, evA, evG2;
    if (!inited) {
        cudaFuncSetAttribute(k_mma_gemm<false, true>,
                             cudaFuncAttributeMaxDynamicSharedMemorySize, GEMM_SMEM);
        cudaFuncSetAttribute(k_mma_gemm<true, false>,
                             cudaFuncAttributeMaxDynamicSharedMemorySize, GEMM_SMEM);
        cudaStreamCreateWithFlags(&s2, cudaStreamNonBlocking);
        cudaEventCreateWithFlags(&evRoot, cudaEventDisableTiming);
        cudaEventCreateWithFlags(&evCsr, cudaEventDisableTiming);
        cudaEventCreateWithFlags(&evA, cudaEventDisableTiming);
        cudaEventCreateWithFlags(&evG2, cudaEventDisableTiming);
        inited = 1;
    }

    // ---- fork ---------------------------------------------------------------
    cudaEventRecord(evRoot, 0);
    cudaStreamWaitEvent(s2, evRoot, 0);

    // main: conversions needed by GEMM1
    k_conv_x<<<(N * K1 + 255) / 256, 256>>>(x, N * K1);
    k_conv_w1<<<(K1 * N1P + 255) / 256, 256>>>(W1);

    // s2: W2 conversion + full CSR build chain (latency-bound, overlaps GEMM1)
    k_conv_w2<<<(K2P * N2P + 255) / 256, 256, 0, s2>>>(W2, H2);
    k_detect<<<1, 32, 0, s2>>>(ei);
    k_init<<<(N + 255) / 256, 256, 0, s2>>>(N);
    k_count_deg<<<(E + 255) / 256, 256, 0, s2>>>(ei, E);
    k_dinv<<<(N + 255) / 256, 256, 0, s2>>>(N);
    int nb = (N + 255) / 256;
    k_scan_blocks<<<nb, 256, 0, s2>>>(deg, rowptr, bsums, N);
    k_scan_sums<<<1, 256, 0, s2>>>(bsums, nb, rowptr + N);
    k_scan_add<<<nb, 256, 0, s2>>>(rowptr, bsums, N);
    k_fill_csr<<<(E + N + 255) / 256, 256, 0, s2>>>(ei, E, N);
    cudaEventRecord(evCsr, s2);

    // main: GEMM1 -> h1 (fp16)
    {
        dim3 grid(N1P / BN, (N + BM - 1) / BM);
        k_mma_gemm<false, true><<<grid, 256, GEMM_SMEM>>>(
            xh, w1h, nullptr, nullptr, h1h, N, F_HID, N1P, K1);
    }

    // ---- join: aggregations need CSR ---------------------------------------
    cudaStreamWaitEvent(0, evCsr, 0);

    // agg1: fp16 gather -> fp16 out (bias + relu)
    k_aggregate<true><<<N, 128>>>(h1h, b1, agg1h, F_HID, 0);

    // agg2 chunk0 -> GEMM2 chunk0 on s2 (overlaps agg2 chunk1)
    k_aggregate<false><<<SPLIT_R, 128>>>(agg1h, nullptr, a2h, K2P, 0);
    cudaEventRecord(evA, 0);
    cudaStreamWaitEvent(s2, evA, 0);
    {
        dim3 grid(N2P / BN, SPLIT_R / BM);
        k_mma_gemm<true, false><<<grid, 256, GEMM_SMEM, s2>>>(
            a2h, w2h, b2, out, nullptr, SPLIT_R, H2, N2P, K2P);
    }
    cudaEventRecord(evG2, s2);

    // main: agg2 chunk1, then GEMM2 chunk1
    k_aggregate<false><<<N - SPLIT_R, 128>>>(agg1h, nullptr, a2h, K2P, SPLIT_R);
    {
        int mrem = N - SPLIT_R;
        dim3 grid(N2P / BN, (mrem + BM - 1) / BM);
        k_mma_gemm<true, false><<<grid, 256, GEMM_SMEM>>>(
            a2h + (size_t)SPLIT_R * K2P, w2h, b2,
            out + (size_t)SPLIT_R * H2, nullptr, mrem, H2, N2P, K2P);
    }
    cudaStreamWaitEvent(0, evG2, 0);
}

// round 14
// speedup vs baseline: 1.5117x; 1.5117x over previous
#include <cuda_runtime.h>
#include <cuda_bf16.h>
#include <cuda_fp16.h>
#include <stdint.h>

// ---------------------------------------------------------------------------
// GCN 2-layer:  out = Anorm @ relu(Anorm @ (x@W1) + b1) @ W2 + b2
// Layer 2 via linearity: (Anorm @ h1relu) @ W2 + b2.
// R14 (= R13 resubmit after infra failure): fp16 GEMMs + 4-stage cp.async
// pipeline (R12 showed mainloop was L2-latency bound at 2 stages: halving
// mma work changed nothing).
// (tcgen05 unavailable: harness compiles compute_103 PTX which rejects it.)
// ---------------------------------------------------------------------------

#define N_NODES 50000
#define M_PAD   50048
#define MAX_E   1600000
#define MAX_CSR (MAX_E + N_NODES)
#define F_HID   400
#define K1      512
#define N1P     512
#define K2P     416
#define N2P     896
#define SPLIT_R 25088          // agg2/GEMM2 chunk boundary (196 * 128)

// GEMM tiling
#define BM 128
#define BN 128
#define BK 32
#define NSTAGE 4
#define AP 40                  // smem A row pitch (halves): 80B, conflict-free ldmatrix
#define BP 136                 // smem B row pitch (halves): 272B, conflict-free ldmatrix
#define GEMM_SMEM ((NSTAGE*BM*AP + NSTAGE*BK*BP) * 2)   // 75776 bytes

// ------------------------------- scratch -----------------------------------
__device__ __half g_h1h[(size_t)N_NODES * F_HID];    // x@W1 (fp16)
__device__ __half g_agg1h[(size_t)N_NODES * F_HID];  // relu(agg(h1)+b1) (fp16)
__device__ __half g_xh[(size_t)M_PAD * K1];          // x (fp16)
__device__ __half g_a2h[(size_t)M_PAD * K2P];        // agg2 (fp16); pad cols stay 0
__device__ __half g_w1h[K1 * N1P];                   // W1 fp16
__device__ __half g_w2h[K2P * N2P];                  // W2 fp16
__device__ float g_dinv[N_NODES];
__device__ int   g_deg[N_NODES];
__device__ int   g_fill[N_NODES];
__device__ int   g_rowptr[N_NODES + 1];
__device__ int   g_csr[MAX_CSR];
__device__ int   g_bsums[512];
__device__ int   g_is64;

// ---------------------------------------------------------------------------
// edge dtype detection (int32 vs int64 delivery)
// ---------------------------------------------------------------------------
__global__ void k_detect(const void* __restrict__ ei) {
    if (threadIdx.x == 0 && blockIdx.x == 0) {
        const long long* p = (const long long*)ei;
        int ok64 = 1;
#pragma unroll
        for (int i = 0; i < 16; i++) {
            long long v = p[i];
            if (v < 0 || v >= N_NODES) ok64 = 0;
        }
        g_is64 = ok64;
    }
}

__device__ __forceinline__ int edge_at(const void* ei, size_t idx) {
    if (g_is64) return (int)((const long long*)ei)[idx];
    return ((const int*)ei)[idx];
}

// ---------------------------------------------------------------------------
// degree / dinv
// ---------------------------------------------------------------------------
__global__ void k_init(int n) {
    int i = blockIdx.x * blockDim.x + threadIdx.x;
    if (i < n) { g_deg[i] = 1; g_fill[i] = 0; }
}

__global__ void k_count_deg(const void* __restrict__ ei, int E) {
    int i = blockIdx.x * blockDim.x + threadIdx.x;
    if (i < E) {
        int d = edge_at(ei, (size_t)E + i);
        if ((unsigned)d < (unsigned)N_NODES) atomicAdd(&g_deg[d], 1);
    }
}

__global__ void k_dinv(int n) {
    int i = blockIdx.x * blockDim.x + threadIdx.x;
    if (i < n) g_dinv[i] = rsqrtf((float)g_deg[i]);
}

// ---------------------------------------------------------------------------
// exclusive scan of g_deg -> g_rowptr
// ---------------------------------------------------------------------------
__device__ __forceinline__ int warp_incl_scan(int v) {
#pragma unroll
    for (int o = 1; o < 32; o <<= 1) {
        int t = __shfl_up_sync(0xffffffffu, v, o);
        if ((threadIdx.x & 31) >= o) v += t;
    }
    return v;
}

__global__ void k_scan_blocks(const int* __restrict__ in, int* __restrict__ out,
                              int* __restrict__ bsums, int n) {
    __shared__ int wsum[8];
    int i = blockIdx.x * 256 + threadIdx.x;
    int v = (i < n) ? in[i] : 0;
    int inc = warp_incl_scan(v);
    int lane = threadIdx.x & 31, w = threadIdx.x >> 5;
    if (lane == 31) wsum[w] = inc;
    __syncthreads();
    if (w == 0) {
        int s = (lane < 8) ? wsum[lane] : 0;
        s = warp_incl_scan(s);
        if (lane < 8) wsum[lane] = s;
    }
    __syncthreads();
    int off = (w > 0) ? wsum[w - 1] : 0;
    if (i < n) out[i] = off + inc - v;
    if (threadIdx.x == 255) bsums[blockIdx.x] = off + inc;
}

__global__ void k_scan_sums(int* __restrict__ bsums, int nb, int* __restrict__ total_out) {
    __shared__ int wsum[8];
    int v = (threadIdx.x < nb) ? bsums[threadIdx.x] : 0;
    int inc = warp_incl_scan(v);
    int lane = threadIdx.x & 31, w = threadIdx.x >> 5;
    if (lane == 31) wsum[w] = inc;
    __syncthreads();
    if (w == 0) {
        int s = (lane < 8) ? wsum[lane] : 0;
        s = warp_incl_scan(s);
        if (lane < 8) wsum[lane] = s;
    }
    __syncthreads();
    int off = (w > 0) ? wsum[w - 1] : 0;
    if (threadIdx.x < nb) bsums[threadIdx.x] = off + inc - v;
    if (threadIdx.x == 255) *total_out = off + inc;
}

__global__ void k_scan_add(int* __restrict__ out, const int* __restrict__ bsums, int n) {
    int i = blockIdx.x * 256 + threadIdx.x;
    if (i < n) out[i] += bsums[blockIdx.x];
}

// ---------------------------------------------------------------------------
// CSR fill
// ---------------------------------------------------------------------------
__global__ void k_fill_csr(const void* __restrict__ ei, int E, int n) {
    int i = blockIdx.x * blockDim.x + threadIdx.x;
    int total = E + n;
    if (i >= total) return;
    int s, d;
    if (i < E) {
        s = edge_at(ei, i);
        d = edge_at(ei, (size_t)E + i);
        if ((unsigned)s >= (unsigned)n || (unsigned)d >= (unsigned)n) return;
    } else {
        s = d = i - E;
    }
    int pos = atomicAdd(&g_fill[d], 1);
    g_csr[g_rowptr[d] + pos] = s;
}

// ---------------------------------------------------------------------------
// fp16 conversions
// ---------------------------------------------------------------------------
__global__ void k_conv_x(const float* __restrict__ x, int total) {
    int i = blockIdx.x * blockDim.x + threadIdx.x;
    if (i < total) g_xh[i] = __float2half(x[i]);
}

__global__ void k_conv_w1(const float* __restrict__ W1) {
    int i = blockIdx.x * blockDim.x + threadIdx.x;
    if (i < K1 * N1P) {
        int k = i / N1P, n = i % N1P;
        float v = (n < F_HID) ? W1[k * F_HID + n] : 0.f;
        g_w1h[i] = __float2half(v);
    }
}

__global__ void k_conv_w2(const float* __restrict__ W2, int N2real) {
    int i = blockIdx.x * blockDim.x + threadIdx.x;
    if (i < K2P * N2P) {
        int k = i / N2P, n = i % N2P;
        float v = (k < F_HID && n < N2real) ? W2[k * N2real + n] : 0.f;
        g_w2h[i] = __float2half(v);
    }
}

// ---------------------------------------------------------------------------
// plain fp16 tensor-core GEMM, 4-stage cp.async pipeline
// ---------------------------------------------------------------------------
__device__ __forceinline__ void cp16(void* dst, const void* src) {
    unsigned d = (unsigned)__cvta_generic_to_shared(dst);
    asm volatile("cp.async.cg.shared.global [%0], [%1], 16;\n" :: "r"(d), "l"(src));
}

__device__ __forceinline__ void ldmA(uint32_t* a, const __half* p) {
    unsigned addr = (unsigned)__cvta_generic_to_shared(p);
    asm volatile("ldmatrix.sync.aligned.m8n8.x4.shared.b16 {%0,%1,%2,%3}, [%4];"
                 : "=r"(a[0]), "=r"(a[1]), "=r"(a[2]), "=r"(a[3]) : "r"(addr));
}

__device__ __forceinline__ void ldmB(uint32_t* b, const __half* p) {
    unsigned addr = (unsigned)__cvta_generic_to_shared(p);
    asm volatile("ldmatrix.sync.aligned.m8n8.x2.trans.shared.b16 {%0,%1}, [%2];"
                 : "=r"(b[0]), "=r"(b[1]) : "r"(addr));
}

__device__ __forceinline__ void mma_fp16(float* c, const uint32_t* a, const uint32_t* b) {
    asm volatile("mma.sync.aligned.m16n8k16.row.col.f32.f16.f16.f32 "
                 "{%0,%1,%2,%3}, {%4,%5,%6,%7}, {%8,%9}, {%0,%1,%2,%3};"
                 : "+f"(c[0]), "+f"(c[1]), "+f"(c[2]), "+f"(c[3])
                 : "r"(a[0]), "r"(a[1]), "r"(a[2]), "r"(a[3]), "r"(b[0]), "r"(b[1]));
}

template <bool BIAS, bool HOUT>
__global__ __launch_bounds__(256, 1) void k_mma_gemm(
    const __half* __restrict__ A, const __half* __restrict__ B,
    const float* __restrict__ bias, float* __restrict__ C, __half* __restrict__ Ch,
    int M, int Nreal, int Nphys, int K) {
    extern __shared__ __half smem[];
    __half* sA = smem;                       // NSTAGE * BM*AP
    __half* sB = sA + NSTAGE * BM * AP;      // NSTAGE * BK*BP

    int tid = threadIdx.x;
    int lane = tid & 31, wid = tid >> 5;
    int wm = (wid >> 2) * 64;
    int wn = (wid & 3) * 32;
    int bm = blockIdx.y * BM, bn = blockIdx.x * BN;

    float acc[4][4][4];
#pragma unroll
    for (int i = 0; i < 4; i++)
#pragma unroll
        for (int j = 0; j < 4; j++)
#pragma unroll
            for (int k = 0; k < 4; k++) acc[i][j][k] = 0.f;

    const int nk = K / BK;

    auto load_stage = [&](int st, int kt) {
        __half* sa = sA + st * BM * AP;
        __half* sb = sB + st * BK * BP;
#pragma unroll
        for (int i = 0; i < 2; i++) {
            int q = tid + i * 256;           // 512 chunks: 128 rows x 4x16B
            int r = q >> 2, c = q & 3;
            size_t goff = (size_t)(bm + r) * K + kt * BK + c * 8;
            cp16(sa + r * AP + c * 8, A + goff);
        }
#pragma unroll
        for (int i = 0; i < 2; i++) {
            int q = tid + i * 256;           // 512 chunks: 32 rows x 16x16B
            int r = q >> 4, c = q & 15;
            size_t goff = (size_t)(kt * BK + r) * Nphys + bn + c * 8;
            cp16(sb + r * BP + c * 8, B + goff);
        }
        asm volatile("cp.async.commit_group;\n");
    };

    // prologue: fill NSTAGE-1 stages
    for (int s = 0; s < NSTAGE - 1 && s < nk; s++) load_stage(s, s);

    for (int kt = 0; kt < nk; kt++) {
        // issue stage kt+NSTAGE-1 (if any), then wait until stage kt resident
        if (kt + NSTAGE - 1 < nk) {
            load_stage((kt + NSTAGE - 1) % NSTAGE, kt + NSTAGE - 1);
            asm volatile("cp.async.wait_group %0;\n" :: "n"(NSTAGE - 1));
        } else {
            int pending = nk - 1 - kt;       // stages kt+1..nk-1 still pending
            if (pending >= 3)      asm volatile("cp.async.wait_group 3;\n");
            else if (pending == 2) asm volatile("cp.async.wait_group 2;\n");
            else if (pending == 1) asm volatile("cp.async.wait_group 1;\n");
            else                   asm volatile("cp.async.wait_group 0;\n");
        }
        __syncthreads();

        int st = kt % NSTAGE;
        const __half* sa = sA + st * BM * AP;
        const __half* sb = sB + st * BK * BP;

#pragma unroll
        for (int ks = 0; ks < 2; ks++) {
            uint32_t Af[4][4], Bf[4][2];
            int arow = (lane & 15), ahalf = (lane >> 4);
#pragma unroll
            for (int mt = 0; mt < 4; mt++) {
                const __half* pa =
                    sa + (size_t)(wm + mt * 16 + arow) * AP + ks * 16 + ahalf * 8;
                ldmA(Af[mt], pa);
            }
#pragma unroll
            for (int nt = 0; nt < 4; nt++) {
                const __half* pb =
                    sb + (size_t)(ks * 16 + (lane & 15)) * BP + wn + nt * 8;
                ldmB(Bf[nt], pb);
            }
#pragma unroll
            for (int mt = 0; mt < 4; mt++)
#pragma unroll
                for (int nt = 0; nt < 4; nt++)
                    mma_fp16(acc[mt][nt], Af[mt], Bf[nt]);
        }
        __syncthreads();
    }

#pragma unroll
    for (int mt = 0; mt < 4; mt++) {
#pragma unroll
        for (int nt = 0; nt < 4; nt++) {
#pragma unroll
            for (int i = 0; i < 4; i++) {
                int row = bm + wm + mt * 16 + (lane >> 2) + (i >> 1) * 8;
                int col = bn + wn + nt * 8 + (lane & 3) * 2 + (i & 1);
                if (row < M && col < Nreal) {
                    float v = acc[mt][nt][i];
                    if (BIAS) v += bias[col];
                    if (HOUT) Ch[(size_t)row * Nreal + col] = __float2half(v);
                    else      C[(size_t)row * Nreal + col] = v;
                }
            }
        }
    }
}

// ---------------------------------------------------------------------------
// CSR aggregation over F=400 fp16 features, one block (128 thr) per node.
// 100 lanes x uint2 (4 halves, LDG.64) per edge; fp32 accumulation.
// OS = output row stride (F_HID for agg1, K2P for agg2).
// ---------------------------------------------------------------------------
template <bool RELU>
__global__ __launch_bounds__(128) void k_aggregate(
    const __half* __restrict__ H, const float* __restrict__ bias,
    __half* __restrict__ outH, int OS, int node0) {
    __shared__ int   s_idx[128];
    __shared__ float s_w[128];

    int node = blockIdx.x + node0;
    int tid = threadIdx.x;
    int start = g_rowptr[node], end = g_rowptr[node + 1];
    float dd = g_dinv[node];

    float4 acc = make_float4(0.f, 0.f, 0.f, 0.f);
    const bool active = tid < (F_HID / 4);   // 100 uint2 lanes

    for (int base = start; base < end; base += 128) {
        int cnt = min(128, end - base);
        if (tid < cnt) {
            int s = g_csr[base + tid];
            s_idx[tid] = s;
            s_w[tid] = g_dinv[s] * dd;
        }
        __syncthreads();
        if (active) {
            int j = 0;
            for (; j + 4 <= cnt; j += 4) {
                uint2 u0 = ((const uint2*)(H + (size_t)s_idx[j + 0] * F_HID))[tid];
                uint2 u1 = ((const uint2*)(H + (size_t)s_idx[j + 1] * F_HID))[tid];
                uint2 u2 = ((const uint2*)(H + (size_t)s_idx[j + 2] * F_HID))[tid];
                uint2 u3 = ((const uint2*)(H + (size_t)s_idx[j + 3] * F_HID))[tid];
                float w0 = s_w[j + 0], w1 = s_w[j + 1];
                float w2 = s_w[j + 2], w3 = s_w[j + 3];
                float2 a0 = __half22float2(*(__half2*)&u0.x);
                float2 b0 = __half22float2(*(__half2*)&u0.y);
                float2 a1 = __half22float2(*(__half2*)&u1.x);
                float2 b1 = __half22float2(*(__half2*)&u1.y);
                float2 a2 = __half22float2(*(__half2*)&u2.x);
                float2 b2 = __half22float2(*(__half2*)&u2.y);
                float2 a3 = __half22float2(*(__half2*)&u3.x);
                float2 b3 = __half22float2(*(__half2*)&u3.y);
                acc.x += a0.x * w0; acc.y += a0.y * w0;
                acc.z += b0.x * w0; acc.w += b0.y * w0;
                acc.x += a1.x * w1; acc.y += a1.y * w1;
                acc.z += b1.x * w1; acc.w += b1.y * w1;
                acc.x += a2.x * w2; acc.y += a2.y * w2;
                acc.z += b2.x * w2; acc.w += b2.y * w2;
                acc.x += a3.x * w3; acc.y += a3.y * w3;
                acc.z += b3.x * w3; acc.w += b3.y * w3;
            }
            for (; j < cnt; j++) {
                uint2 u0 = ((const uint2*)(H + (size_t)s_idx[j] * F_HID))[tid];
                float w0 = s_w[j];
                float2 a0 = __half22float2(*(__half2*)&u0.x);
                float2 b0 = __half22float2(*(__half2*)&u0.y);
                acc.x += a0.x * w0; acc.y += a0.y * w0;
                acc.z += b0.x * w0; acc.w += b0.y * w0;
            }
        }
        __syncthreads();
    }

    if (active) {
        if (bias) {
            float4 b = ((const float4*)bias)[tid];
            acc.x += b.x; acc.y += b.y; acc.z += b.z; acc.w += b.w;
        }
        if (RELU) {
            acc.x = fmaxf(acc.x, 0.f); acc.y = fmaxf(acc.y, 0.f);
            acc.z = fmaxf(acc.z, 0.f); acc.w = fmaxf(acc.w, 0.f);
        }
        __half2 h01 = __floats2half2_rn(acc.x, acc.y);
        __half2 h23 = __floats2half2_rn(acc.z, acc.w);
        uint2 u;
        u.x = *(uint32_t*)&h01; u.y = *(uint32_t*)&h23;
        *(uint2*)(outH + (size_t)node * OS + tid * 4) = u;
    }
}

// ---------------------------------------------------------------------------
// launch
// ---------------------------------------------------------------------------
extern "C" void kernel_launch(void* const* d_in, const int* in_sizes, int n_in,
                              void* d_out, int out_size) {
    const float* x  = (const float*)d_in[0];
    const void*  ei = d_in[1];
    const float* W1 = (const float*)d_in[2];
    const float* b1 = (const float*)d_in[3];
    const float* W2 = (const float*)d_in[4];
    const float* b2 = (const float*)d_in[5];
    float* out = (float*)d_out;

    const int N = N_NODES;
    const int E = in_sizes[1] / 2;
    const int H2 = in_sizes[5];                       // 800

    __half *h1h, *agg1h, *xh, *a2h, *w1h, *w2h;
    int *deg, *rowptr, *bsums;
    cudaGetSymbolAddress((void**)&h1h, g_h1h);
    cudaGetSymbolAddress((void**)&agg1h, g_agg1h);
    cudaGetSymbolAddress((void**)&xh, g_xh);
    cudaGetSymbolAddress((void**)&a2h, g_a2h);
    cudaGetSymbolAddress((void**)&w1h, g_w1h);
    cudaGetSymbolAddress((void**)&w2h, g_w2h);
    cudaGetSymbolAddress((void**)&deg, g_deg);
    cudaGetSymbolAddress((void**)&rowptr, g_rowptr);
    cudaGetSymbolAddress((void**)&bsums, g_bsums);

    static int inited = 0;
    static cudaStream_t s2;
    static cudaEvent_t evRoot, evCsr, evA, evG2;
    if (!inited) {
        cudaFuncSetAttribute(k_mma_gemm<false, true>,
                             cudaFuncAttributeMaxDynamicSharedMemorySize, GEMM_SMEM);
        cudaFuncSetAttribute(k_mma_gemm<true, false>,
                             cudaFuncAttributeMaxDynamicSharedMemorySize, GEMM_SMEM);
        cudaStreamCreateWithFlags(&s2, cudaStreamNonBlocking);
        cudaEventCreateWithFlags(&evRoot, cudaEventDisableTiming);
        cudaEventCreateWithFlags(&evCsr, cudaEventDisableTiming);
        cudaEventCreateWithFlags(&evA, cudaEventDisableTiming);
        cudaEventCreateWithFlags(&evG2, cudaEventDisableTiming);
        inited = 1;
    }

    // ---- fork ---------------------------------------------------------------
    cudaEventRecord(evRoot, 0);
    cudaStreamWaitEvent(s2, evRoot, 0);

    // main: conversions needed by GEMM1
    k_conv_x<<<(N * K1 + 255) / 256, 256>>>(x, N * K1);
    k_conv_w1<<<(K1 * N1P + 255) / 256, 256>>>(W1);

    // s2: W2 conversion + full CSR build chain (latency-bound, overlaps GEMM1)
    k_conv_w2<<<(K2P * N2P + 255) / 256, 256, 0, s2>>>(W2, H2);
    k_detect<<<1, 32, 0, s2>>>(ei);
    k_init<<<(N + 255) / 256, 256, 0, s2>>>(N);
    k_count_deg<<<(E + 255) / 256, 256, 0, s2>>>(ei, E);
    k_dinv<<<(N + 255) / 256, 256, 0, s2>>>(N);
    int nb = (N + 255) / 256;
    k_scan_blocks<<<nb, 256, 0, s2>>>(deg, rowptr, bsums, N);
    k_scan_sums<<<1, 256, 0, s2>>>(bsums, nb, rowptr + N);
    k_scan_add<<<nb, 256, 0, s2>>>(rowptr, bsums, N);
    k_fill_csr<<<(E + N + 255) / 256, 256, 0, s2>>>(ei, E, N);
    cudaEventRecord(evCsr, s2);

    // main: GEMM1 -> h1 (fp16)
    {
        dim3 grid(N1P / BN, (N + BM - 1) / BM);
        k_mma_gemm<false, true><<<grid, 256, GEMM_SMEM>>>(
            xh, w1h, nullptr, nullptr, h1h, N, F_HID, N1P, K1);
    }

    // ---- join: aggregations need CSR ---------------------------------------
    cudaStreamWaitEvent(0, evCsr, 0);

    // agg1: fp16 gather -> fp16 out (bias + relu)
    k_aggregate<true><<<N, 128>>>(h1h, b1, agg1h, F_HID, 0);

    // agg2 chunk0 -> GEMM2 chunk0 on s2 (overlaps agg2 chunk1)
    k_aggregate<false><<<SPLIT_R, 128>>>(agg1h, nullptr, a2h, K2P, 0);
    cudaEventRecord(evA, 0);
    cudaStreamWaitEvent(s2, evA, 0);
    {
        dim3 grid(N2P / BN, SPLIT_R / BM);
        k_mma_gemm<true, false><<<grid, 256, GEMM_SMEM, s2>>>(
            a2h, w2h, b2, out, nullptr, SPLIT_R, H2, N2P, K2P);
    }
    cudaEventRecord(evG2, s2);

    // main: agg2 chunk1, then GEMM2 chunk1
    k_aggregate<false><<<N - SPLIT_R, 128>>>(agg1h, nullptr, a2h, K2P, SPLIT_R);
    {
        int mrem = N - SPLIT_R;
        dim3 grid(N2P / BN, (mrem + BM - 1) / BM);
        k_mma_gemm<true, false><<<grid, 256, GEMM_SMEM>>>(
            a2h + (size_t)SPLIT_R * K2P, w2h, b2,
            out + (size_t)SPLIT_R * H2, nullptr, mrem, H2, N2P, K2P);
    }
    cudaStreamWaitEvent(0, evG2, 0);
}